// round 3
// baseline (speedup 1.0000x reference)
#include <cuda_runtime.h>
#include <cstdint>

// Chamfer distance, B=4,S=4 pairs, N=M=4096 3D points.
// Single fused kernel, no scratch: each block stages the FULL target set
// (64KB SoA: x,y,z,h=0.5*|t|^2) and evaluates 512 queries (256 thr x QPT=2)
// against it with packed fma.rn.f32x2 (2 evals / 3 FFMA2). Running mins on
// the ALU pipe (FMNMX). Block-reduced sums accumulate into out[S,B] via one
// atomicAdd per block; out is zeroed by a memset graph node.

#define BDIM 4
#define SDIM 4
#define NPAIRS 16
#define THREADS 256
#define QPT 2

__device__ __forceinline__ uint64_t fma2(uint64_t a, uint64_t b, uint64_t c) {
    uint64_t d;
    asm("fma.rn.f32x2 %0, %1, %2, %3;" : "=l"(d) : "l"(a), "l"(b), "l"(c));
    return d;
}
__device__ __forceinline__ uint64_t pack2(float lo, float hi) {
    uint64_t d;
    asm("mov.b64 %0, {%1, %2};" : "=l"(d) : "f"(lo), "f"(hi));
    return d;
}
__device__ __forceinline__ void unpack2(uint64_t v, float& lo, float& hi) {
    asm("mov.b64 {%0, %1}, %2;" : "=f"(lo), "=f"(hi) : "l"(v));
}

extern __shared__ float s_mem[];

__global__ __launch_bounds__(THREADS)
void chamfer_main(const float* __restrict__ outp,
                  const float* __restrict__ tgtp,
                  int Nq, int Mt, int Ts,
                  float* __restrict__ out) {
    const int dir  = blockIdx.z;    // 0: out->tgt, 1: tgt->out
    const int pair = blockIdx.y;

    const float* qpts = dir ? tgtp : outp;
    const float* tpts = dir ? outp : tgtp;
    const int nq = dir ? Mt : Nq;
    const int mt = dir ? Nq : Mt;

    float* sx = s_mem;
    float* sy = s_mem + Ts;
    float* sz = s_mem + 2 * Ts;
    float* sh = s_mem + 3 * Ts;

    // ---- stage full target set: SoA + half squared norm ----
    const float* tbase = tpts + (size_t)pair * mt * 3;
    for (int j = threadIdx.x; j < mt; j += THREADS) {
        float a = tbase[3 * j + 0];
        float b = tbase[3 * j + 1];
        float c = tbase[3 * j + 2];
        sx[j] = a; sy[j] = b; sz[j] = c;
        sh[j] = 0.5f * (a * a + b * b + c * c);
    }
    for (int j = mt + threadIdx.x; j < Ts; j += THREADS) {
        sx[j] = 0.f; sy[j] = 0.f; sz[j] = 0.f; sh[j] = 3.0e37f;  // sentinel
    }
    __syncthreads();

    // ---- query register setup (negated, packed {v,v}) ----
    uint64_t nx[QPT], ny[QPT], nz[QPT];
    float x2[QPT], mlo[QPT], mhi[QPT];
    const float* qbase = qpts + (size_t)pair * nq * 3;
    const int q0 = blockIdx.x * (THREADS * QPT) + threadIdx.x;
#pragma unroll
    for (int k = 0; k < QPT; k++) {
        int qi = q0 + k * THREADS;
        float a = 0.f, b = 0.f, c = 0.f;
        if (qi < nq) {
            a = qbase[3 * qi + 0];
            b = qbase[3 * qi + 1];
            c = qbase[3 * qi + 2];
        }
        nx[k] = pack2(-a, -a);
        ny[k] = pack2(-b, -b);
        nz[k] = pack2(-c, -c);
        x2[k] = a * a + b * b + c * c;
        mlo[k] = 3.0e37f;
        mhi[k] = 3.0e37f;
    }

    // ---- main loop: 4 targets / iter via LDS.128 + packed f32x2 FMA ----
    const ulonglong2* pX = (const ulonglong2*)sx;
    const ulonglong2* pY = (const ulonglong2*)sy;
    const ulonglong2* pZ = (const ulonglong2*)sz;
    const ulonglong2* pH = (const ulonglong2*)sh;
    const int iters = Ts >> 2;
#pragma unroll 2
    for (int j = 0; j < iters; j++) {
        ulonglong2 BX = pX[j];
        ulonglong2 BY = pY[j];
        ulonglong2 BZ = pZ[j];
        ulonglong2 HH = pH[j];
#pragma unroll
        for (int k = 0; k < QPT; k++) {
            uint64_t t0 = fma2(nx[k], BX.x, HH.x);
            t0 = fma2(ny[k], BY.x, t0);
            t0 = fma2(nz[k], BZ.x, t0);
            uint64_t t1 = fma2(nx[k], BX.y, HH.y);
            t1 = fma2(ny[k], BY.y, t1);
            t1 = fma2(nz[k], BZ.y, t1);
            float a0, a1, b0, b1;
            unpack2(t0, a0, a1);
            unpack2(t1, b0, b1);
            mlo[k] = fminf(mlo[k], a0);
            mhi[k] = fminf(mhi[k], a1);
            mlo[k] = fminf(mlo[k], b0);
            mhi[k] = fminf(mhi[k], b1);
        }
    }

    // ---- finalize: d2 = max(x2 + 2*min, 0); sum this thread's queries ----
    float lsum = 0.f;
#pragma unroll
    for (int k = 0; k < QPT; k++) {
        int qi = q0 + k * THREADS;
        if (qi < nq) {
            float t = fminf(mlo[k], mhi[k]);
            lsum += fmaxf(fmaf(2.0f, t, x2[k]), 0.0f);
        }
    }

    // ---- block reduce, one atomicAdd per block ----
#pragma unroll
    for (int off = 16; off; off >>= 1)
        lsum += __shfl_down_sync(0xffffffffu, lsum, off);

    __shared__ float red[THREADS / 32];
    const int wid = threadIdx.x >> 5;
    if ((threadIdx.x & 31) == 0) red[wid] = lsum;
    __syncthreads();
    if (threadIdx.x == 0) {
        float tot = 0.f;
#pragma unroll
        for (int w = 0; w < THREADS / 32; w++) tot += red[w];
        int b = pair / SDIM;
        int s = pair % SDIM;
        atomicAdd(out + s * BDIM + b, tot / (float)nq);
    }
}

extern "C" void kernel_launch(void* const* d_in, const int* in_sizes, int n_in,
                              void* d_out, int out_size) {
    const float* outp = (const float*)d_in[0];  // [B,S,N,3]
    const float* tgtp = (const float*)d_in[1];  // [B,S,M,3]
    float* out = (float*)d_out;                  // [S,B]

    const int Nq = in_sizes[0] / (NPAIRS * 3);
    const int Mt = in_sizes[1] / (NPAIRS * 3);
    const int maxP = Nq > Mt ? Nq : Mt;
    const int Ts = (maxP + 3) & ~3;                  // multiple of 4 for LDS.128
    const size_t smem = (size_t)4 * Ts * sizeof(float);

    cudaFuncSetAttribute(chamfer_main,
                         cudaFuncAttributeMaxDynamicSharedMemorySize, (int)smem);

    cudaMemsetAsync(out, 0, (size_t)out_size * sizeof(float));

    const int qpb = THREADS * QPT;  // 512 queries per block
    dim3 grid((maxP + qpb - 1) / qpb, NPAIRS, 2);
    chamfer_main<<<grid, THREADS, smem>>>(outp, tgtp, Nq, Mt, Ts, out);
}